// round 2
// baseline (speedup 1.0000x reference)
#include <cuda_runtime.h>
#include <math.h>

#define NCELL 49
#define NBOX  98
#define NC    20
#define THREADS 640
#define ROWS  (NBOX * NC)      // 1960
#define OUTF  (ROWS * 6)       // 11760

__global__ __launch_bounds__(THREADS, 3)
void yolo_head_kernel(const float* __restrict__ x, float* __restrict__ out)
{
    __shared__ float prob[NCELL][NC];          // softmax class probs per cell
    __shared__ float confs[NBOX];              // per-box confidence
    __shared__ float bx[NBOX][4];              // pixel boxes
    __shared__ float area[NBOX];               // box areas
    __shared__ float sT[NC][112];              // scores, class-major (padded)
    __shared__ unsigned int SUP[NBOX][4];      // suppression bitmask: SUP[a] = {b : iou(a,b) > 0.5}
    __shared__ unsigned char order_[NC][112];  // per-class sorted order (desc score, stable)
    __shared__ unsigned int keepm[NC][4];      // per-class keep bitmask (pre score-threshold)

    const int tid = threadIdx.x;
    const int b   = blockIdx.x;
    const float* __restrict__ xb = x + (size_t)b * (NCELL * 30);

    // ---- Phase 1: softmax per cell (threads 0..48) ----
    if (tid < NCELL) {
        float v[NC];
        float mx = -INFINITY;
        #pragma unroll
        for (int c = 0; c < NC; c++) { v[c] = xb[tid * 30 + c]; mx = fmaxf(mx, v[c]); }
        float s = 0.0f;
        #pragma unroll
        for (int c = 0; c < NC; c++) { v[c] = expf(__fsub_rn(v[c], mx)); s = __fadd_rn(s, v[c]); }
        #pragma unroll
        for (int c = 0; c < NC; c++) prob[tid][c] = __fdiv_rn(v[c], s);
    }

    // ---- Phase 2: decode boxes (threads 0..97) ----
    if (tid < NBOX) {
        const int cell = tid >> 1, bb = tid & 1;
        const int gi = cell / 7, gj = cell % 7;       // gy = row i, gx = col j
        const float* p = xb + cell * 30;
        const float tx = p[20 + bb * 4 + 0];
        const float ty = p[20 + bb * 4 + 1];
        const float w  = p[20 + bb * 4 + 2];
        const float h  = p[20 + bb * 4 + 3];
        confs[tid] = p[28 + bb];

        const float cx = __fdiv_rn(__fadd_rn(tx, (float)gj), 7.0f);
        const float cy = __fdiv_rn(__fadd_rn(ty, (float)gi), 7.0f);
        const float hw = __fmul_rn(w, 0.5f);          // w/2 (exact: /2)
        const float hh = __fmul_rn(h, 0.5f);
        float x1 = __fsub_rn(cx, hw), y1 = __fsub_rn(cy, hh);
        float x2 = __fadd_rn(cx, hw), y2 = __fadd_rn(cy, hh);
        x1 = __fmul_rn(fminf(fmaxf(x1, 0.0f), 1.0f), 448.0f);
        y1 = __fmul_rn(fminf(fmaxf(y1, 0.0f), 1.0f), 448.0f);
        x2 = __fmul_rn(fminf(fmaxf(x2, 0.0f), 1.0f), 448.0f);
        y2 = __fmul_rn(fminf(fmaxf(y2, 0.0f), 1.0f), 448.0f);
        bx[tid][0] = x1; bx[tid][1] = y1; bx[tid][2] = x2; bx[tid][3] = y2;
        area[tid] = __fmul_rn(fmaxf(__fsub_rn(x2, x1), 0.0f),
                              fmaxf(__fsub_rn(y2, y1), 0.0f));
    }
    __syncthreads();

    // ---- Phase 3: scores (class-major for conflict-free broadcast reads) ----
    for (int idx = tid; idx < ROWS; idx += THREADS) {
        const int n = idx % NBOX, c = idx / NBOX;
        sT[c][n] = __fmul_rn(prob[n >> 1][c], confs[n]);
    }

    // ---- Phase 4: suppression bitmask, one (row, word) task per thread ----
    if (tid < NBOX * 4) {
        const int a = tid >> 2, wd = tid & 3;
        const float ax1 = bx[a][0], ay1 = bx[a][1], ax2 = bx[a][2], ay2 = bx[a][3];
        const float aa  = area[a];
        unsigned int m = 0;
        const int base = wd * 32;
        #pragma unroll 4
        for (int k = 0; k < 32; k++) {
            const int bi = base + k;
            if (bi >= NBOX) break;
            const float ix1 = fmaxf(ax1, bx[bi][0]);
            const float iy1 = fmaxf(ay1, bx[bi][1]);
            const float ix2 = fminf(ax2, bx[bi][2]);
            const float iy2 = fminf(ay2, bx[bi][3]);
            const float inter = __fmul_rn(fmaxf(__fsub_rn(ix2, ix1), 0.0f),
                                          fmaxf(__fsub_rn(iy2, iy1), 0.0f));
            const float uni = __fsub_rn(__fadd_rn(aa, area[bi]), inter);
            const float iou = __fdiv_rn(inter, fmaxf(uni, 1e-9f));
            if (iou > 0.5f) m |= (1u << k);
        }
        SUP[a][wd] = m;
    }
    __syncthreads();

    // ---- Phase 5: per-class stable rank -> order (warp w handles class w) ----
    const int w = tid >> 5, lane = tid & 31;   // w in [0,20)
    #pragma unroll
    for (int rep = 0; rep < 4; rep++) {
        const int n = lane + rep * 32;
        if (n < NBOX) {
            const float sn = sT[w][n];
            int r = 0;
            for (int m = 0; m < NBOX; m++) {
                const float sm = sT[w][m];        // broadcast load
                r += (sm > sn) || (sm == sn && m < n);
            }
            order_[w][r] = (unsigned char)n;      // ranks are unique (total order)
        }
    }
    __syncwarp();

    // ---- Phase 6: serial NMS bit-loop (lane 0 of each class warp) ----
    if (lane == 0) {
        unsigned long long aliveLo = ~0ULL, aliveHi = ~0ULL;
        unsigned long long keepLo = 0ULL,  keepHi = 0ULL;
        for (int i = 0; i < NBOX; i++) {
            const int a = order_[w][i];
            const unsigned long long supLo =
                (unsigned long long)SUP[a][0] | ((unsigned long long)SUP[a][1] << 32);
            const unsigned long long supHi =
                (unsigned long long)SUP[a][2] | ((unsigned long long)SUP[a][3] << 32);
            bool alive_a;
            if (a < 64) alive_a = (aliveLo >> a) & 1ULL;
            else        alive_a = (aliveHi >> (a - 64)) & 1ULL;
            if (alive_a) {
                if (a < 64) keepLo |= (1ULL << a);
                else        keepHi |= (1ULL << (a - 64));
                aliveLo &= ~supLo;
                aliveHi &= ~supHi;
            }
        }
        keepm[w][0] = (unsigned int)(keepLo);
        keepm[w][1] = (unsigned int)(keepLo >> 32);
        keepm[w][2] = (unsigned int)(keepHi);
        keepm[w][3] = (unsigned int)(keepHi >> 32);
    }
    __syncthreads();

    // ---- Phase 7: coalesced output write (48 MB total; the roofline term) ----
    float* __restrict__ ob = out + (size_t)b * OUTF;
    for (int idx = tid; idx < OUTF; idx += THREADS) {
        const int row = idx / 6, k = idx - row * 6;
        const int n = row / NC, c = row - n * NC;
        const float sc = sT[c][n];
        const unsigned int kb = (keepm[c][n >> 5] >> (n & 31)) & 1u;
        const float kf = (kb && (sc >= 0.05f)) ? 1.0f : 0.0f;
        float v;
        if (k == 0)      v = (float)c;
        else if (k == 5) v = sc;
        else             v = bx[n][k - 1];
        ob[idx] = __fmul_rn(v, kf);
    }
}

extern "C" void kernel_launch(void* const* d_in, const int* in_sizes, int n_in,
                              void* d_out, int out_size)
{
    const float* x = (const float*)d_in[0];
    float* out = (float*)d_out;
    const int B = in_sizes[0] / (NCELL * 30);   // 1024
    yolo_head_kernel<<<B, THREADS>>>(x, out);
}

// round 3
// speedup vs baseline: 1.4602x; 1.4602x over previous
#include <cuda_runtime.h>
#include <math.h>

#define NCELL 49
#define NBOX  98
#define NC    20
#define THREADS 640
#define ROWS  (NBOX * NC)      // 1960
#define OUTF  (ROWS * 6)       // 11760
#define STP   113              // padded score stride (kills bank conflicts in P7)

__global__ __launch_bounds__(THREADS, 3)
void yolo_head_kernel(const float* __restrict__ x, float* __restrict__ out)
{
    __shared__ float  prob[NCELL][NC];        // softmax class probs per cell
    __shared__ float  confs[NBOX];            // per-box confidence
    __shared__ float4 bx4[NBOX];              // pixel boxes (16B aligned rows)
    __shared__ float  area[NBOX];             // box areas
    __shared__ float  sT[NC][STP];            // scores, class-major, padded
    __shared__ uint2  SG[NBOX * 4];           // {sup_word, own_bit} per (box, word-group)
    __shared__ unsigned char order_[NC][112]; // per-class rank -> box index
    __shared__ unsigned int  keepm[NC][5];    // per-class keep bitmask (padded stride)

    const int tid  = threadIdx.x;
    const int lane = tid & 31;
    const int w    = tid >> 5;                // warp id == class id (20 warps)
    const int b    = blockIdx.x;
    const float* __restrict__ xb = x + (size_t)b * (NCELL * 30);

    // ---- Phase 1: softmax per cell (threads 0..48) ----
    if (tid < NCELL) {
        float v[NC];
        float mx = -INFINITY;
        #pragma unroll
        for (int c = 0; c < NC; c++) { v[c] = xb[tid * 30 + c]; mx = fmaxf(mx, v[c]); }
        float s = 0.0f;
        #pragma unroll
        for (int c = 0; c < NC; c++) { v[c] = expf(__fsub_rn(v[c], mx)); s = __fadd_rn(s, v[c]); }
        #pragma unroll
        for (int c = 0; c < NC; c++) prob[tid][c] = __fdiv_rn(v[c], s);
    }

    // ---- Phase 2: decode boxes (threads 0..97) ----
    if (tid < NBOX) {
        const int cell = tid >> 1, bb = tid & 1;
        const int gi = cell / 7, gj = cell % 7;
        const float* p = xb + cell * 30;
        const float tx = p[20 + bb * 4 + 0];
        const float ty = p[20 + bb * 4 + 1];
        const float ww = p[20 + bb * 4 + 2];
        const float hh = p[20 + bb * 4 + 3];
        confs[tid] = p[28 + bb];

        const float cx = __fdiv_rn(__fadd_rn(tx, (float)gj), 7.0f);
        const float cy = __fdiv_rn(__fadd_rn(ty, (float)gi), 7.0f);
        const float hw = __fmul_rn(ww, 0.5f);
        const float hl = __fmul_rn(hh, 0.5f);
        float x1 = __fsub_rn(cx, hw), y1 = __fsub_rn(cy, hl);
        float x2 = __fadd_rn(cx, hw), y2 = __fadd_rn(cy, hl);
        x1 = __fmul_rn(fminf(fmaxf(x1, 0.0f), 1.0f), 448.0f);
        y1 = __fmul_rn(fminf(fmaxf(y1, 0.0f), 1.0f), 448.0f);
        x2 = __fmul_rn(fminf(fmaxf(x2, 0.0f), 1.0f), 448.0f);
        y2 = __fmul_rn(fminf(fmaxf(y2, 0.0f), 1.0f), 448.0f);
        bx4[tid] = make_float4(x1, y1, x2, y2);
        area[tid] = __fmul_rn(fmaxf(__fsub_rn(x2, x1), 0.0f),
                              fmaxf(__fsub_rn(y2, y1), 0.0f));
    }
    __syncthreads();

    // ---- Phase 3: scores class-major (all threads) ----
    for (int idx = tid; idx < ROWS; idx += THREADS) {
        const int c = idx / NBOX, n = idx - c * NBOX;
        sT[c][n] = __fmul_rn(prob[n >> 1][c], confs[n]);
    }

    // ---- Phase 4: suppression words + ownership bit (threads 0..391) ----
    if (tid < NBOX * 4) {
        const int a = tid >> 2, wd = tid & 3;
        const float4 A = bx4[a];
        const float aa = area[a];
        unsigned int m = 0;
        const int base = wd * 32;
        const int lim  = (base + 32 <= NBOX) ? 32 : (NBOX - base);
        #pragma unroll 4
        for (int k = 0; k < lim; k++) {
            const int bi = base + k;
            const float4 Bb = bx4[bi];
            const float ix1 = fmaxf(A.x, Bb.x);
            const float iy1 = fmaxf(A.y, Bb.y);
            const float ix2 = fminf(A.z, Bb.z);
            const float iy2 = fminf(A.w, Bb.w);
            const float inter = __fmul_rn(fmaxf(__fsub_rn(ix2, ix1), 0.0f),
                                          fmaxf(__fsub_rn(iy2, iy1), 0.0f));
            const float uni = __fsub_rn(__fadd_rn(aa, area[bi]), inter);
            const float iou = __fdiv_rn(inter, fmaxf(uni, 1e-9f));
            if (iou > 0.5f) m |= (1u << k);
        }
        SG[a * 4 + wd] = make_uint2(m, (wd == (a >> 5)) ? (1u << (a & 31)) : 0u);
    }
    __syncthreads();

    // ---- Phase 5: per-class rank (fast strict path + rare tie fallback) ----
    const int n0 = lane, n1 = lane + 32, n2 = lane + 64, n3 = lane + 96;
    const float sn0 = sT[w][n0];
    const float sn1 = sT[w][n1];
    const float sn2 = sT[w][n2];
    const float sn3 = (n3 < NBOX) ? sT[w][n3] : INFINITY;
    {
        float r0 = 0.f, r1 = 0.f, r2 = 0.f, r3 = 0.f;
        #pragma unroll 14
        for (int m = 0; m < NBOX; m++) {
            const float sm = sT[w][m];
            r0 = __fadd_rn(r0, (sm > sn0) ? 1.0f : 0.0f);
            r1 = __fadd_rn(r1, (sm > sn1) ? 1.0f : 0.0f);
            r2 = __fadd_rn(r2, (sm > sn2) ? 1.0f : 0.0f);
            r3 = __fadd_rn(r3, (sm > sn3) ? 1.0f : 0.0f);
        }
        // init to sentinel, scatter strict ranks
        order_[w][lane]      = 0xFF;
        order_[w][lane + 32] = 0xFF;
        order_[w][lane + 64] = 0xFF;
        if (lane < 16) order_[w][lane + 96] = 0xFF;
        __syncwarp();
        order_[w][(int)r0] = (unsigned char)n0;
        order_[w][(int)r1] = (unsigned char)n1;
        order_[w][(int)r2] = (unsigned char)n2;
        if (n3 < NBOX) order_[w][(int)r3] = (unsigned char)n3;
        __syncwarp();
        // collision => ties existed => exact (stable) fallback
        bool bad = (order_[w][lane] == 0xFF) |
                   (order_[w][lane + 32] == 0xFF) |
                   (order_[w][lane + 64] == 0xFF) |
                   ((lane < 2) && (order_[w][lane + 96] == 0xFF));
        if (__ballot_sync(0xffffffffu, bad)) {
            int e0 = 0, e1 = 0, e2 = 0, e3 = 0;
            for (int m = 0; m < NBOX; m++) {
                const float sm = sT[w][m];
                e0 += (sm > sn0) || (sm == sn0 && m < n0);
                e1 += (sm > sn1) || (sm == sn1 && m < n1);
                e2 += (sm > sn2) || (sm == sn2 && m < n2);
                e3 += (sm > sn3) || (sm == sn3 && m < n3);
            }
            order_[w][e0] = (unsigned char)n0;
            order_[w][e1] = (unsigned char)n1;
            order_[w][e2] = (unsigned char)n2;
            if (n3 < NBOX) order_[w][e3] = (unsigned char)n3;
            __syncwarp();
        }
    }

    // ---- Phase 6: warp-parallel greedy NMS bit-loop ----
    {
        const int grp = lane & 3;               // which 32-bit word this lane owns
        unsigned int alive = 0xffffffffu, keep = 0u;
        #pragma unroll 7
        for (int i = 0; i < NBOX; i++) {
            const int a = order_[w][i];         // uniform across warp
            const uint2 s = SG[a * 4 + grp];    // {sup_word, own_bit}
            const bool pred = (alive & s.y) != 0u;       // true only on owner grp & alive
            const unsigned int v = __ballot_sync(0xffffffffu, pred);
            if (v)    alive &= ~s.x;            // box a kept -> suppress its overlaps
            if (pred) keep  |= s.y;
        }
        if (lane < 4) keepm[w][lane] = keep;
    }
    __syncthreads();

    // ---- Phase 7: one output row per thread, 3x STG.64 ----
    float* __restrict__ ob = out + (size_t)b * OUTF;
    for (int row = tid; row < ROWS; row += THREADS) {
        const int n = row / NC;
        const int c = row - n * NC;
        const float sc = sT[c][n];
        const unsigned int kb = (keepm[c][n >> 5] >> (n & 31)) & 1u;
        const float kf = (kb && (sc >= 0.05f)) ? 1.0f : 0.0f;
        const float4 bb = bx4[n];
        float* p = ob + row * 6;
        float2 v0, v1, v2;
        v0.x = __fmul_rn((float)c, kf); v0.y = __fmul_rn(bb.x, kf);
        v1.x = __fmul_rn(bb.y, kf);     v1.y = __fmul_rn(bb.z, kf);
        v2.x = __fmul_rn(bb.w, kf);     v2.y = __fmul_rn(sc, kf);
        ((float2*)p)[0] = v0;
        ((float2*)p)[1] = v1;
        ((float2*)p)[2] = v2;
    }
}

extern "C" void kernel_launch(void* const* d_in, const int* in_sizes, int n_in,
                              void* d_out, int out_size)
{
    const float* x = (const float*)d_in[0];
    float* out = (float*)d_out;
    const int B = in_sizes[0] / (NCELL * 30);   // 1024
    yolo_head_kernel<<<B, THREADS>>>(x, out);
}

// round 4
// speedup vs baseline: 2.6096x; 1.7872x over previous
#include <cuda_runtime.h>
#include <math.h>

#define NCELL 49
#define NBOX  98
#define NC    20
#define THREADS 640
#define ROWS  (NBOX * NC)      // 1960
#define OUTF  (ROWS * 6)       // 11760
#define STP   113              // padded score stride

__global__ __launch_bounds__(THREADS, 3)
void yolo_head_kernel(const float* __restrict__ x, float* __restrict__ out)
{
    __shared__ float  prob[NCELL][NC];        // softmax class probs per cell
    __shared__ float  confs[NBOX];            // per-box confidence
    __shared__ float4 bx4[NBOX];              // pixel boxes
    __shared__ float  area[NBOX];             // box areas
    __shared__ float  sT[NC][STP];            // scores, class-major, padded
    __shared__ uint2  SG[NBOX * 4];           // {sup_word, own_bit} per (box, word)
    __shared__ unsigned char ordV[NC][112];   // per-class rank -> box id (involved only)
    __shared__ unsigned int  keepm[NC][5];    // per-class keep bitmask
    __shared__ unsigned char Lst[112];        // compacted involved-box list
    __shared__ unsigned int  invMask[4];      // involved bitmask (class-independent)
    __shared__ int nV;                        // |V|

    const int tid  = threadIdx.x;
    const int lane = tid & 31;
    const int w    = tid >> 5;                // warp id == class id (20 warps)
    const int b    = blockIdx.x;
    const float* __restrict__ xb = x + (size_t)b * (NCELL * 30);

    if (tid == 0) nV = 0;

    // ---- Phase 1: softmax per cell (threads 0..48) ----
    if (tid < NCELL) {
        float v[NC];
        float mx = -INFINITY;
        #pragma unroll
        for (int c = 0; c < NC; c++) { v[c] = xb[tid * 30 + c]; mx = fmaxf(mx, v[c]); }
        float s = 0.0f;
        #pragma unroll
        for (int c = 0; c < NC; c++) { v[c] = expf(__fsub_rn(v[c], mx)); s = __fadd_rn(s, v[c]); }
        #pragma unroll
        for (int c = 0; c < NC; c++) prob[tid][c] = __fdiv_rn(v[c], s);
    }

    // ---- Phase 2: decode boxes (threads 0..97) ----
    if (tid < NBOX) {
        const int cell = tid >> 1, bb = tid & 1;
        const int gi = cell / 7, gj = cell % 7;
        const float* p = xb + cell * 30;
        const float tx = p[20 + bb * 4 + 0];
        const float ty = p[20 + bb * 4 + 1];
        const float ww = p[20 + bb * 4 + 2];
        const float hh = p[20 + bb * 4 + 3];
        confs[tid] = p[28 + bb];

        const float cx = __fdiv_rn(__fadd_rn(tx, (float)gj), 7.0f);
        const float cy = __fdiv_rn(__fadd_rn(ty, (float)gi), 7.0f);
        const float hw = __fmul_rn(ww, 0.5f);
        const float hl = __fmul_rn(hh, 0.5f);
        float x1 = __fsub_rn(cx, hw), y1 = __fsub_rn(cy, hl);
        float x2 = __fadd_rn(cx, hw), y2 = __fadd_rn(cy, hl);
        x1 = __fmul_rn(fminf(fmaxf(x1, 0.0f), 1.0f), 448.0f);
        y1 = __fmul_rn(fminf(fmaxf(y1, 0.0f), 1.0f), 448.0f);
        x2 = __fmul_rn(fminf(fmaxf(x2, 0.0f), 1.0f), 448.0f);
        y2 = __fmul_rn(fminf(fmaxf(y2, 0.0f), 1.0f), 448.0f);
        bx4[tid] = make_float4(x1, y1, x2, y2);
        area[tid] = __fmul_rn(fmaxf(__fsub_rn(x2, x1), 0.0f),
                              fmaxf(__fsub_rn(y2, y1), 0.0f));
    }
    __syncthreads();

    // ---- Phase 3: scores class-major ----
    for (int idx = tid; idx < ROWS; idx += THREADS) {
        const int c = idx / NBOX, n = idx - c * NBOX;
        sT[c][n] = __fmul_rn(prob[n >> 1][c], confs[n]);
    }

    // ---- Phase 4: suppression words + ownership bit (threads 0..391) ----
    if (tid < NBOX * 4) {
        const int a = tid >> 2, wd = tid & 3;
        const float4 A = bx4[a];
        const float aa = area[a];
        unsigned int m = 0;
        const int base = wd * 32;
        const int lim  = (base + 32 <= NBOX) ? 32 : (NBOX - base);
        #pragma unroll 4
        for (int k = 0; k < lim; k++) {
            const int bi = base + k;
            const float4 Bb = bx4[bi];
            const float ix1 = fmaxf(A.x, Bb.x);
            const float iy1 = fmaxf(A.y, Bb.y);
            const float ix2 = fminf(A.z, Bb.z);
            const float iy2 = fminf(A.w, Bb.w);
            const float inter = __fmul_rn(fmaxf(__fsub_rn(ix2, ix1), 0.0f),
                                          fmaxf(__fsub_rn(iy2, iy1), 0.0f));
            const float uni = __fsub_rn(__fadd_rn(aa, area[bi]), inter);
            const float iou = __fdiv_rn(inter, fmaxf(uni, 1e-9f));
            if (iou > 0.5f) m |= (1u << k);
        }
        SG[a * 4 + wd] = make_uint2(m, (wd == (a >> 5)) ? (1u << (a & 31)) : 0u);
    }
    __syncthreads();

    // ---- Phase 4b: involved-set compaction (warps 0..3, one lane per box) ----
    if (w < 4) {
        const int a = tid;                    // 0..127
        bool flag = false;
        if (a < NBOX) {
            const unsigned int own = 1u << (a & 31);
            const int ow = a >> 5;
            unsigned int any = 0;
            #pragma unroll
            for (int wd = 0; wd < 4; wd++) {
                unsigned int mw = SG[a * 4 + wd].x;
                if (wd == ow) mw &= ~own;     // ignore self-overlap
                any |= mw;
            }
            flag = (any != 0);                // symmetric matrix => row test suffices
        }
        const unsigned int bal = __ballot_sync(0xffffffffu, flag);
        if (lane == 0) invMask[w] = bal;
        if (flag) {
            const int p = atomicAdd(&nV, 1);  // list order irrelevant (re-ranked below)
            Lst[p] = (unsigned char)a;
        }
    }
    __syncthreads();

    // ---- Phase 5: per-class exact rank over involved set only ----
    const int v = nV;
    for (int i = lane; i < v; i += 32) {
        const int   ai = Lst[i];
        const float si = sT[w][ai];
        int r = 0;
        for (int j = 0; j < v; j++) {
            const int   aj = Lst[j];          // uniform -> broadcast LDS
            const float sj = sT[w][aj];
            r += (sj > si) || (sj == si && aj < ai);   // stable: score desc, index asc
        }
        ordV[w][r] = (unsigned char)ai;
    }
    __syncwarp();

    // ---- Phase 6: warp-parallel greedy NMS over involved set ----
    {
        const int grp = lane & 3;
        unsigned int alive = 0xffffffffu, keep = 0u;
        for (int i = 0; i < v; i++) {
            const int a = ordV[w][i];
            const uint2 s = SG[a * 4 + grp];
            const bool pred = (alive & s.y) != 0u;
            const unsigned int vb = __ballot_sync(0xffffffffu, pred);
            if (vb)   alive &= ~s.x;
            if (pred) keep  |= s.y;
        }
        if (lane < 4) keepm[w][lane] = (~invMask[lane]) | keep;  // non-involved: always kept
    }
    __syncthreads();

    // ---- Phase 7: one output row per thread, 3x STG.64 ----
    float* __restrict__ ob = out + (size_t)b * OUTF;
    for (int row = tid; row < ROWS; row += THREADS) {
        const int n = row / NC;
        const int c = row - n * NC;
        const float sc = sT[c][n];
        const unsigned int kb = (keepm[c][n >> 5] >> (n & 31)) & 1u;
        const float kf = (kb && (sc >= 0.05f)) ? 1.0f : 0.0f;
        const float4 bb = bx4[n];
        float* p = ob + row * 6;
        float2 v0, v1, v2;
        v0.x = __fmul_rn((float)c, kf); v0.y = __fmul_rn(bb.x, kf);
        v1.x = __fmul_rn(bb.y, kf);     v1.y = __fmul_rn(bb.z, kf);
        v2.x = __fmul_rn(bb.w, kf);     v2.y = __fmul_rn(sc, kf);
        ((float2*)p)[0] = v0;
        ((float2*)p)[1] = v1;
        ((float2*)p)[2] = v2;
    }
}

extern "C" void kernel_launch(void* const* d_in, const int* in_sizes, int n_in,
                              void* d_out, int out_size)
{
    const float* x = (const float*)d_in[0];
    float* out = (float*)d_out;
    const int B = in_sizes[0] / (NCELL * 30);   // 1024
    yolo_head_kernel<<<B, THREADS>>>(x, out);
}

// round 5
// speedup vs baseline: 3.1464x; 1.2057x over previous
#include <cuda_runtime.h>
#include <math.h>

#define NCELL 49
#define NBOX  98
#define NC    20
#define THREADS 640
#define ROWS  (NBOX * NC)      // 1960
#define OUTF  (ROWS * 6)       // 11760
#define STP   113              // padded score stride

__global__ __launch_bounds__(THREADS, 3)
void yolo_head_kernel(const float* __restrict__ x, float* __restrict__ out)
{
    __shared__ float  prob[NCELL][NC];        // softmax class probs per cell
    __shared__ float  confs[NBOX];            // per-box confidence
    __shared__ float4 bx4[NBOX];              // pixel boxes
    __shared__ float  area[NBOX];             // box areas
    __shared__ float  sT[NC][STP];            // scores, class-major, padded
    __shared__ uint2  SG[NBOX * 4];           // {sup_word, own_bit} per (box, word)
    __shared__ unsigned char ordV[NC][112];   // per-class rank -> box id (involved only)
    __shared__ unsigned int  keepm[NC][5];    // per-class keep bitmask
    __shared__ unsigned char Plst[112];       // boxes with area > 0
    __shared__ unsigned char Vlst[112];       // boxes with >=1 overlap edge
    __shared__ unsigned char rowAny[112];     // per-box: has off-diagonal edge
    __shared__ unsigned int  invMask[4];      // V bitmask (class-independent)
    __shared__ int nP, nV;

    const int tid  = threadIdx.x;
    const int lane = tid & 31;
    const int w    = tid >> 5;                // warp id == class id (20 warps)
    const int b    = blockIdx.x;
    const float* __restrict__ xb = x + (size_t)b * (NCELL * 30);

    if (tid == 0) { nP = 0; nV = 0; }
    if (tid < 112) rowAny[tid] = 0;

    // ---- Phase 1: softmax, warp-per-cell (lane c = class c) ----
    #pragma unroll
    for (int r = 0; r < 3; r++) {
        const int cell = w + 20 * r;
        if (cell < NCELL) {
            const float v = (lane < NC) ? xb[cell * 30 + lane] : -INFINITY;
            float mx = v;
            #pragma unroll
            for (int o = 16; o; o >>= 1) mx = fmaxf(mx, __shfl_xor_sync(0xffffffffu, mx, o));
            const float e = (lane < NC) ? expf(__fsub_rn(v, mx)) : 0.0f;
            float s = e;
            #pragma unroll
            for (int o = 16; o; o >>= 1) s = __fadd_rn(s, __shfl_xor_sync(0xffffffffu, s, o));
            if (lane < NC) prob[cell][lane] = __fdiv_rn(e, s);
        }
    }

    // ---- Phase 2: decode boxes (threads 0..97) ----
    if (tid < NBOX) {
        const int cell = tid >> 1, bb = tid & 1;
        const int gi = cell / 7, gj = cell % 7;
        const float* p = xb + cell * 30;
        const float tx = p[20 + bb * 4 + 0];
        const float ty = p[20 + bb * 4 + 1];
        const float ww = p[20 + bb * 4 + 2];
        const float hh = p[20 + bb * 4 + 3];
        confs[tid] = p[28 + bb];

        const float cx = __fdiv_rn(__fadd_rn(tx, (float)gj), 7.0f);
        const float cy = __fdiv_rn(__fadd_rn(ty, (float)gi), 7.0f);
        const float hw = __fmul_rn(ww, 0.5f);
        const float hl = __fmul_rn(hh, 0.5f);
        float x1 = __fsub_rn(cx, hw), y1 = __fsub_rn(cy, hl);
        float x2 = __fadd_rn(cx, hw), y2 = __fadd_rn(cy, hl);
        x1 = __fmul_rn(fminf(fmaxf(x1, 0.0f), 1.0f), 448.0f);
        y1 = __fmul_rn(fminf(fmaxf(y1, 0.0f), 1.0f), 448.0f);
        x2 = __fmul_rn(fminf(fmaxf(x2, 0.0f), 1.0f), 448.0f);
        y2 = __fmul_rn(fminf(fmaxf(y2, 0.0f), 1.0f), 448.0f);
        bx4[tid] = make_float4(x1, y1, x2, y2);
        area[tid] = __fmul_rn(fmaxf(__fsub_rn(x2, x1), 0.0f),
                              fmaxf(__fsub_rn(y2, y1), 0.0f));
    }
    __syncthreads();

    // ---- Phase 2b: compact P = {a : area > 0} (warps 0..3) ----
    if (w < 4) {
        const int a = tid;                       // 0..127
        const bool pos = (a < NBOX) && (area[a] > 0.0f);
        if (pos) {
            const int p = atomicAdd(&nP, 1);     // order irrelevant
            Plst[p] = (unsigned char)a;
        }
    }

    // ---- Phase 3: scores class-major (all threads) ----
    for (int idx = tid; idx < ROWS; idx += THREADS) {
        const int c = idx / NBOX, n = idx - c * NBOX;
        sT[c][n] = __fmul_rn(prob[n >> 1][c], confs[n]);
    }
    __syncthreads();

    // ---- Phase 4: sparse IOU — one thread per P-row, loop over P ----
    const int np = nP;
    if (tid < np) {
        const int a = Plst[tid];
        const float4 A = bx4[a];
        const float aa = area[a];
        unsigned long long lo = 0ULL, hi = 0ULL;
        bool any = false;
        for (int j = 0; j < np; j++) {
            const int bi = Plst[j];
            const float4 Bb = bx4[bi];
            const float ix1 = fmaxf(A.x, Bb.x);
            const float iy1 = fmaxf(A.y, Bb.y);
            const float ix2 = fminf(A.z, Bb.z);
            const float iy2 = fminf(A.w, Bb.w);
            const float inter = __fmul_rn(fmaxf(__fsub_rn(ix2, ix1), 0.0f),
                                          fmaxf(__fsub_rn(iy2, iy1), 0.0f));
            const float uni = __fsub_rn(__fadd_rn(aa, area[bi]), inter);
            const float iou = __fdiv_rn(inter, fmaxf(uni, 1e-9f));
            if (iou > 0.5f) {
                if (bi < 64) lo |= (1ULL << bi);
                else         hi |= (1ULL << (bi - 64));
                any |= (bi != a);
            }
        }
        rowAny[a] = any ? 1 : 0;
        const unsigned int m0 = (unsigned int)lo;
        const unsigned int m1 = (unsigned int)(lo >> 32);
        const unsigned int m2 = (unsigned int)hi;
        const unsigned int m3 = (unsigned int)(hi >> 32);
        const int ow = a >> 5;
        const unsigned int ob = 1u << (a & 31);
        SG[a * 4 + 0] = make_uint2(m0, ow == 0 ? ob : 0u);
        SG[a * 4 + 1] = make_uint2(m1, ow == 1 ? ob : 0u);
        SG[a * 4 + 2] = make_uint2(m2, ow == 2 ? ob : 0u);
        SG[a * 4 + 3] = make_uint2(m3, ow == 3 ? ob : 0u);
    }
    __syncthreads();

    // ---- Phase 4b: compact V = {a : rowAny[a]} (warps 0..3) ----
    if (w < 4) {
        const int a = tid;
        const bool flag = (a < NBOX) && rowAny[a];
        const unsigned int bal = __ballot_sync(0xffffffffu, flag);
        if (lane == 0) invMask[w] = bal;
        if (flag) {
            const int p = atomicAdd(&nV, 1);
            Vlst[p] = (unsigned char)a;
        }
    }
    __syncthreads();

    // ---- Phase 5: per-class exact rank over V ----
    const int v = nV;
    for (int i = lane; i < v; i += 32) {
        const int   ai = Vlst[i];
        const float si = sT[w][ai];
        int r = 0;
        for (int j = 0; j < v; j++) {
            const int   aj = Vlst[j];            // uniform -> broadcast LDS
            const float sj = sT[w][aj];
            r += (sj > si) || (sj == si && aj < ai);
        }
        ordV[w][r] = (unsigned char)ai;
    }
    __syncwarp();

    // ---- Phase 6: warp-parallel greedy NMS over V ----
    {
        const int grp = lane & 3;
        unsigned int alive = 0xffffffffu, keep = 0u;
        for (int i = 0; i < v; i++) {
            const int a = ordV[w][i];
            const uint2 s = SG[a * 4 + grp];
            const bool pred = (alive & s.y) != 0u;
            const unsigned int vb = __ballot_sync(0xffffffffu, pred);
            if (vb)   alive &= ~s.x;
            if (pred) keep  |= s.y;
        }
        if (lane < 4) keepm[w][lane] = (~invMask[lane]) | keep;
    }
    __syncthreads();

    // ---- Phase 7: one output row per thread, 3x STG.64 ----
    float* __restrict__ ob = out + (size_t)b * OUTF;
    for (int row = tid; row < ROWS; row += THREADS) {
        const int n = row / NC;
        const int c = row - n * NC;
        const float sc = sT[c][n];
        const unsigned int kb = (keepm[c][n >> 5] >> (n & 31)) & 1u;
        const float kf = (kb && (sc >= 0.05f)) ? 1.0f : 0.0f;
        const float4 bb = bx4[n];
        float* p = ob + row * 6;
        float2 v0, v1, v2;
        v0.x = __fmul_rn((float)c, kf); v0.y = __fmul_rn(bb.x, kf);
        v1.x = __fmul_rn(bb.y, kf);     v1.y = __fmul_rn(bb.z, kf);
        v2.x = __fmul_rn(bb.w, kf);     v2.y = __fmul_rn(sc, kf);
        ((float2*)p)[0] = v0;
        ((float2*)p)[1] = v1;
        ((float2*)p)[2] = v2;
    }
}

extern "C" void kernel_launch(void* const* d_in, const int* in_sizes, int n_in,
                              void* d_out, int out_size)
{
    const float* x = (const float*)d_in[0];
    float* out = (float*)d_out;
    const int B = in_sizes[0] / (NCELL * 30);   // 1024
    yolo_head_kernel<<<B, THREADS>>>(x, out);
}

// round 6
// speedup vs baseline: 4.7563x; 1.5117x over previous
#include <cuda_runtime.h>
#include <math.h>

#define NCELL 49
#define NBOX  98
#define NC    20
#define THREADS 256
#define ROWS  (NBOX * NC)      // 1960
#define OUTF  (ROWS * 6)       // 11760

__global__ __launch_bounds__(THREADS, 8)
void yolo_head_kernel(const float* __restrict__ x, float* __restrict__ out)
{
    __shared__ float  prob[NCELL][NC];        // softmax class probs per cell
    __shared__ float  confs[NBOX];            // per-box confidence
    __shared__ float4 bx4[NBOX];              // pixel boxes
    __shared__ float  area[NBOX];             // box areas
    __shared__ uint2  SG[NBOX * 4];           // {sup_word, own_bit} per (box, word)
    __shared__ unsigned char ordV[8][112];    // per-warp rank->box scratch
    __shared__ unsigned int  keepm[NC][5];    // per-class keep bitmask (padded)
    __shared__ unsigned char Plst[112];       // boxes with area > 0
    __shared__ unsigned char Vlst[112];       // boxes with >=1 overlap edge
    __shared__ unsigned char rowAny[112];
    __shared__ unsigned int  invMask[4];      // V bitmask
    __shared__ int nP, nV;

    const int tid  = threadIdx.x;
    const int lane = tid & 31;
    const int w    = tid >> 5;                // 8 warps
    const int b    = blockIdx.x;
    const float* __restrict__ xb = x + (size_t)b * (NCELL * 30);

    if (tid == 0) { nP = 0; nV = 0; }
    if (tid < 112) rowAny[tid] = 0;

    // ---- Phase 1: softmax, thread-per-cell (threads 0..48) ----
    if (tid < NCELL) {
        float v[NC];
        float mx = -INFINITY;
        #pragma unroll
        for (int c = 0; c < NC; c++) { v[c] = xb[tid * 30 + c]; mx = fmaxf(mx, v[c]); }
        float s = 0.0f;
        #pragma unroll
        for (int c = 0; c < NC; c++) { v[c] = expf(__fsub_rn(v[c], mx)); s = __fadd_rn(s, v[c]); }
        #pragma unroll
        for (int c = 0; c < NC; c++) prob[tid][c] = __fdiv_rn(v[c], s);
    }

    // ---- Phase 2: decode boxes (threads 64..161 -> avoid softmax warps) ----
    if (tid >= 64 && tid < 64 + NBOX) {
        const int n = tid - 64;
        const int cell = n >> 1, bb = n & 1;
        const int gi = cell / 7, gj = cell % 7;
        const float* p = xb + cell * 30;
        const float tx = p[20 + bb * 4 + 0];
        const float ty = p[20 + bb * 4 + 1];
        const float ww = p[20 + bb * 4 + 2];
        const float hh = p[20 + bb * 4 + 3];
        confs[n] = p[28 + bb];

        const float cx = __fdiv_rn(__fadd_rn(tx, (float)gj), 7.0f);
        const float cy = __fdiv_rn(__fadd_rn(ty, (float)gi), 7.0f);
        const float hw = __fmul_rn(ww, 0.5f);
        const float hl = __fmul_rn(hh, 0.5f);
        float x1 = __fsub_rn(cx, hw), y1 = __fsub_rn(cy, hl);
        float x2 = __fadd_rn(cx, hw), y2 = __fadd_rn(cy, hl);
        x1 = __fmul_rn(fminf(fmaxf(x1, 0.0f), 1.0f), 448.0f);
        y1 = __fmul_rn(fminf(fmaxf(y1, 0.0f), 1.0f), 448.0f);
        x2 = __fmul_rn(fminf(fmaxf(x2, 0.0f), 1.0f), 448.0f);
        y2 = __fmul_rn(fminf(fmaxf(y2, 0.0f), 1.0f), 448.0f);
        bx4[n] = make_float4(x1, y1, x2, y2);
        area[n] = __fmul_rn(fmaxf(__fsub_rn(x2, x1), 0.0f),
                            fmaxf(__fsub_rn(y2, y1), 0.0f));
    }
    __syncthreads();

    // ---- Phase 2b: compact P = {a : area > 0} (warps 0..3) ----
    if (w < 4) {
        const int a = tid;                       // 0..127
        const bool pos = (a < NBOX) && (area[a] > 0.0f);
        if (pos) {
            const int p = atomicAdd(&nP, 1);     // order irrelevant
            Plst[p] = (unsigned char)a;
        }
    }
    __syncthreads();

    // ---- Phase 4: sparse IOU — one thread per P-row, loop over P ----
    const int np = nP;
    if (tid < np) {
        const int a = Plst[tid];
        const float4 A = bx4[a];
        const float aa = area[a];
        unsigned long long lo = 0ULL, hi = 0ULL;
        bool any = false;
        for (int j = 0; j < np; j++) {
            const int bi = Plst[j];
            const float4 Bb = bx4[bi];
            const float ix1 = fmaxf(A.x, Bb.x);
            const float iy1 = fmaxf(A.y, Bb.y);
            const float ix2 = fminf(A.z, Bb.z);
            const float iy2 = fminf(A.w, Bb.w);
            const float inter = __fmul_rn(fmaxf(__fsub_rn(ix2, ix1), 0.0f),
                                          fmaxf(__fsub_rn(iy2, iy1), 0.0f));
            const float uni = __fsub_rn(__fadd_rn(aa, area[bi]), inter);
            const float iou = __fdiv_rn(inter, fmaxf(uni, 1e-9f));
            if (iou > 0.5f) {
                if (bi < 64) lo |= (1ULL << bi);
                else         hi |= (1ULL << (bi - 64));
                any |= (bi != a);
            }
        }
        rowAny[a] = any ? 1 : 0;
        const int ow = a >> 5;
        const unsigned int ob = 1u << (a & 31);
        SG[a * 4 + 0] = make_uint2((unsigned int)lo,         ow == 0 ? ob : 0u);
        SG[a * 4 + 1] = make_uint2((unsigned int)(lo >> 32), ow == 1 ? ob : 0u);
        SG[a * 4 + 2] = make_uint2((unsigned int)hi,         ow == 2 ? ob : 0u);
        SG[a * 4 + 3] = make_uint2((unsigned int)(hi >> 32), ow == 3 ? ob : 0u);
    }
    __syncthreads();

    // ---- Phase 4b: compact V = {a : rowAny[a]} (warps 0..3) ----
    if (w < 4) {
        const int a = tid;
        const bool flag = (a < NBOX) && rowAny[a];
        const unsigned int bal = __ballot_sync(0xffffffffu, flag);
        if (lane == 0) invMask[w] = bal;
        if (flag) {
            const int p = atomicAdd(&nV, 1);
            Vlst[p] = (unsigned char)a;
        }
    }
    __syncthreads();

    // ---- Phase 5+6: per-class rank + NMS, classes w, w+8, w+16 per warp ----
    const int v = nV;
    #pragma unroll
    for (int cc = 0; cc < 3; cc++) {
        const int c = w + 8 * cc;
        if (c >= NC) break;
        // rank over V (stable: score desc, index asc); scores recomputed
        for (int i = lane; i < v; i += 32) {
            const int   ai = Vlst[i];
            const float si = __fmul_rn(prob[ai >> 1][c], confs[ai]);
            int r = 0;
            for (int j = 0; j < v; j++) {
                const int   aj = Vlst[j];            // uniform -> broadcast
                const float sj = __fmul_rn(prob[aj >> 1][c], confs[aj]);
                r += (sj > si) || (sj == si && aj < ai);
            }
            ordV[w][r] = (unsigned char)ai;
        }
        __syncwarp();
        // warp-parallel greedy NMS over V
        {
            const int grp = lane & 3;
            unsigned int alive = 0xffffffffu, keep = 0u;
            for (int i = 0; i < v; i++) {
                const int a = ordV[w][i];
                const uint2 s = SG[a * 4 + grp];
                const bool pred = (alive & s.y) != 0u;
                const unsigned int vb = __ballot_sync(0xffffffffu, pred);
                if (vb)   alive &= ~s.x;
                if (pred) keep  |= s.y;
            }
            if (lane < 4) keepm[c][lane] = (~invMask[lane]) | keep;
        }
        __syncwarp();
    }
    __syncthreads();

    // ---- Phase 7: one output row per thread, 3x STG.64 ----
    float* __restrict__ ob = out + (size_t)b * OUTF;
    for (int row = tid; row < ROWS; row += THREADS) {
        const int n = row / NC;
        const int c = row - n * NC;
        const float sc = __fmul_rn(prob[n >> 1][c], confs[n]);
        const unsigned int kb = (keepm[c][n >> 5] >> (n & 31)) & 1u;
        const float kf = (kb && (sc >= 0.05f)) ? 1.0f : 0.0f;
        const float4 bb = bx4[n];
        float* p = ob + row * 6;
        float2 v0, v1, v2;
        v0.x = __fmul_rn((float)c, kf); v0.y = __fmul_rn(bb.x, kf);
        v1.x = __fmul_rn(bb.y, kf);     v1.y = __fmul_rn(bb.z, kf);
        v2.x = __fmul_rn(bb.w, kf);     v2.y = __fmul_rn(sc, kf);
        ((float2*)p)[0] = v0;
        ((float2*)p)[1] = v1;
        ((float2*)p)[2] = v2;
    }
}

extern "C" void kernel_launch(void* const* d_in, const int* in_sizes, int n_in,
                              void* d_out, int out_size)
{
    const float* x = (const float*)d_in[0];
    float* out = (float*)d_out;
    const int B = in_sizes[0] / (NCELL * 30);   // 1024
    yolo_head_kernel<<<B, THREADS>>>(x, out);
}